// round 1
// baseline (speedup 1.0000x reference)
#include <cuda_runtime.h>

// GAE backward scan, shape (B=8192, T=256, A=4, 1), fp32.
//   delta_t = r_t + gamma * nv_t * nd_t - v_t
//   gae_t   = delta_t + gamma*lambda * nd_t * gae_{t+1}   (gae_T = 0)
//   adv_t   = gae_t ;  ret_t = gae_t + v_t
// Outputs concatenated: [advantages (B*T*A), returns (B*T*A)].

#define GAMMA_F  0.99f
#define LAMBDA_F 0.95f

constexpr int B = 8192;
constexpr int T = 256;
constexpr int A = 4;
constexpr int ROW4 = T * A / 4;     // float4 per batch row = 256

constexpr int BB = 32;              // batches per block
constexpr int TC = 16;              // t-steps per chunk
constexpr int THREADS = BB * A;     // 128 threads (one per sequence)
constexpr int SROW = TC * A + 4;    // 68 floats: pad so bank = (4bb+4dt+a)%32 (conflict-free)
constexpr int LOADS = (BB * TC) / THREADS;  // float4 loads per thread per tile = 4

__global__ __launch_bounds__(THREADS)
void gae_kernel(const float4* __restrict__ reward,
                const float4* __restrict__ term,
                const float4* __restrict__ value,
                const float4* __restrict__ nxtval,
                float4* __restrict__ adv_out,
                float4* __restrict__ ret_out)
{
    __shared__ float s_delta[BB * SROW];
    __shared__ float s_nd   [BB * SROW];
    __shared__ float s_val  [BB * SROW];
    __shared__ float s_adv  [BB * SROW];
    __shared__ float s_ret  [BB * SROW];

    const int tid = threadIdx.x;
    const int b0  = blockIdx.x * BB;
    const int bb  = tid >> 2;       // local batch for recurrence phase
    const int a   = tid & 3;        // agent

    float gae = 0.0f;

    for (int t0 = T - TC; t0 >= 0; t0 -= TC) {
        // ---- stage: coalesced float4 loads, compute delta & nd on the fly ----
        #pragma unroll
        for (int k = 0; k < LOADS; k++) {
            const int f   = tid + k * THREADS;   // 0..511
            const int row = f >> 4;              // local batch
            const int col = f & 15;              // t-step within chunk (1 float4 == 1 step)
            const int g   = (b0 + row) * ROW4 + t0 + col;

            const float4 r  = reward[g];
            const float4 tm = term[g];
            const float4 v  = value[g];
            const float4 nv = nxtval[g];

            float4 nd, dl;
            nd.x = 1.0f - tm.x;  nd.y = 1.0f - tm.y;
            nd.z = 1.0f - tm.z;  nd.w = 1.0f - tm.w;
            dl.x = fmaf(GAMMA_F * nv.x, nd.x, r.x) - v.x;
            dl.y = fmaf(GAMMA_F * nv.y, nd.y, r.y) - v.y;
            dl.z = fmaf(GAMMA_F * nv.z, nd.z, r.z) - v.z;
            dl.w = fmaf(GAMMA_F * nv.w, nd.w, r.w) - v.w;

            const int s = row * SROW + col * 4;  // 16B-aligned (SROW%4==0)
            *reinterpret_cast<float4*>(&s_delta[s]) = dl;
            *reinterpret_cast<float4*>(&s_nd[s])    = nd;
            *reinterpret_cast<float4*>(&s_val[s])   = v;
        }
        __syncthreads();

        // ---- recurrence: one sequence per thread, backward over the chunk ----
        #pragma unroll
        for (int dt = TC - 1; dt >= 0; dt--) {
            const int s = bb * SROW + dt * 4 + a;
            gae = fmaf((GAMMA_F * LAMBDA_F) * s_nd[s], gae, s_delta[s]);
            s_adv[s] = gae;
            s_ret[s] = gae + s_val[s];
        }
        __syncthreads();

        // ---- drain: coalesced float4 stores ----
        #pragma unroll
        for (int k = 0; k < LOADS; k++) {
            const int f   = tid + k * THREADS;
            const int row = f >> 4;
            const int col = f & 15;
            const int g   = (b0 + row) * ROW4 + t0 + col;
            const int s   = row * SROW + col * 4;
            adv_out[g] = *reinterpret_cast<const float4*>(&s_adv[s]);
            ret_out[g] = *reinterpret_cast<const float4*>(&s_ret[s]);
        }
        __syncthreads();  // protect smem before next chunk's stage overwrites
    }
}

extern "C" void kernel_launch(void* const* d_in, const int* in_sizes, int n_in,
                              void* d_out, int out_size)
{
    const float4* reward = (const float4*)d_in[0];
    const float4* term   = (const float4*)d_in[1];
    const float4* value  = (const float4*)d_in[2];
    const float4* nxtval = (const float4*)d_in[3];

    float* out = (float*)d_out;
    float4* adv = (float4*)out;
    float4* ret = (float4*)(out + (size_t)B * T * A);

    gae_kernel<<<B / BB, THREADS>>>(reward, term, value, nxtval, adv, ret);
}

// round 2
// speedup vs baseline: 1.5118x; 1.5118x over previous
#include <cuda_runtime.h>

// GAE backward scan, (B=8192, T=256, A=4), fp32.
//   delta_t = r_t + gamma*nv_t*nd_t - v_t
//   gae_t   = delta_t + gamma*lambda*nd_t*gae_{t+1}   (gae_T = 0)
//   adv = gae ; ret = gae + v.  Output: [adv | ret].
//
// R2: one-warp blocks (independent phase interleaving across ~7 blocks/SM)
//     + register-prefetch software pipeline to hide DRAM latency behind the
//     serial recurrence.

#define GAMMA_F  0.99f
#define LAMBDA_F 0.95f

constexpr int B = 8192;
constexpr int T = 256;
constexpr int A = 4;
constexpr int ROW4 = T * A / 4;      // 256 float4 per batch row

constexpr int BB = 8;                // batches per block
constexpr int TC = 16;               // t-steps per chunk
constexpr int THREADS = BB * A;      // 32 = one warp
constexpr int SROW = TC * A + 4;     // 68: bank = (4bb+4dt+a)%32, conflict-free
constexpr int K = (BB * TC) / THREADS;  // float4 loads per thread per array = 4

struct Chunk {
    float4 dl[K];
    float4 nd[K];
    float4 v [K];
};

__device__ __forceinline__ Chunk load_chunk(const float4* __restrict__ reward,
                                            const float4* __restrict__ term,
                                            const float4* __restrict__ value,
                                            const float4* __restrict__ nxtval,
                                            int b0, int t0, int lane)
{
    Chunk c;
    #pragma unroll
    for (int k = 0; k < K; k++) {
        const int f   = lane + k * THREADS;
        const int row = f >> 4;
        const int col = f & 15;
        const int g   = (b0 + row) * ROW4 + t0 + col;

        const float4 r  = reward[g];
        const float4 tm = term[g];
        const float4 v  = value[g];
        const float4 nv = nxtval[g];

        float4 nd, dl;
        nd.x = 1.0f - tm.x;  nd.y = 1.0f - tm.y;
        nd.z = 1.0f - tm.z;  nd.w = 1.0f - tm.w;
        dl.x = fmaf(GAMMA_F * nv.x, nd.x, r.x) - v.x;
        dl.y = fmaf(GAMMA_F * nv.y, nd.y, r.y) - v.y;
        dl.z = fmaf(GAMMA_F * nv.z, nd.z, r.z) - v.z;
        dl.w = fmaf(GAMMA_F * nv.w, nd.w, r.w) - v.w;

        c.dl[k] = dl;  c.nd[k] = nd;  c.v[k] = v;
    }
    return c;
}

__global__ __launch_bounds__(THREADS)
void gae_kernel(const float4* __restrict__ reward,
                const float4* __restrict__ term,
                const float4* __restrict__ value,
                const float4* __restrict__ nxtval,
                float4* __restrict__ adv_out,
                float4* __restrict__ ret_out)
{
    __shared__ float s_dl [BB * SROW];
    __shared__ float s_nd [BB * SROW];
    __shared__ float s_v  [BB * SROW];
    __shared__ float s_adv[BB * SROW];

    const int lane = threadIdx.x;
    const int b0   = blockIdx.x * BB;
    const int bb   = lane >> 2;
    const int a    = lane & 3;

    float gae = 0.0f;

    // prologue: prefetch last chunk
    Chunk cur = load_chunk(reward, term, value, nxtval, b0, T - TC, lane);

    #pragma unroll 2
    for (int t0 = T - TC; t0 >= 0; t0 -= TC) {
        // ---- stage current chunk regs -> smem ----
        #pragma unroll
        for (int k = 0; k < K; k++) {
            const int f   = lane + k * THREADS;
            const int row = f >> 4;
            const int col = f & 15;
            const int s   = row * SROW + col * 4;
            *reinterpret_cast<float4*>(&s_dl[s]) = cur.dl[k];
            *reinterpret_cast<float4*>(&s_nd[s]) = cur.nd[k];
            *reinterpret_cast<float4*>(&s_v [s]) = cur.v [k];
        }

        // ---- issue next chunk's LDGs now; latency overlaps recurrence ----
        Chunk nxt;
        if (t0 > 0)
            nxt = load_chunk(reward, term, value, nxtval, b0, t0 - TC, lane);

        __syncwarp();

        // ---- serial backward recurrence (one sequence per lane) ----
        #pragma unroll
        for (int dt = TC - 1; dt >= 0; dt--) {
            const int s = bb * SROW + dt * 4 + a;
            gae = fmaf((GAMMA_F * LAMBDA_F) * s_nd[s], gae, s_dl[s]);
            s_adv[s] = gae;
        }
        __syncwarp();

        // ---- drain: coalesced float4 stores (ret recomputed here) ----
        #pragma unroll
        for (int k = 0; k < K; k++) {
            const int f   = lane + k * THREADS;
            const int row = f >> 4;
            const int col = f & 15;
            const int g   = (b0 + row) * ROW4 + t0 + col;
            const int s   = row * SROW + col * 4;
            const float4 ad = *reinterpret_cast<const float4*>(&s_adv[s]);
            const float4 vv = *reinterpret_cast<const float4*>(&s_v [s]);
            float4 rt;
            rt.x = ad.x + vv.x;  rt.y = ad.y + vv.y;
            rt.z = ad.z + vv.z;  rt.w = ad.w + vv.w;
            adv_out[g] = ad;
            ret_out[g] = rt;
        }
        __syncwarp();  // protect smem before next stage overwrites

        if (t0 > 0) cur = nxt;
    }
}

extern "C" void kernel_launch(void* const* d_in, const int* in_sizes, int n_in,
                              void* d_out, int out_size)
{
    const float4* reward = (const float4*)d_in[0];
    const float4* term   = (const float4*)d_in[1];
    const float4* value  = (const float4*)d_in[2];
    const float4* nxtval = (const float4*)d_in[3];

    float* out = (float*)d_out;
    float4* adv = (float4*)out;
    float4* ret = (float4*)(out + (size_t)B * T * A);

    gae_kernel<<<B / BB, THREADS>>>(reward, term, value, nxtval, adv, ret);
}

// round 3
// speedup vs baseline: 1.6141x; 1.0676x over previous
#include <cuda_runtime.h>

// GAE backward scan, (B=8192, T=256, A=4), fp32.
//   delta_t = r_t + gamma*nv_t*nd_t - v_t
//   gae_t   = delta_t + gamma*lambda*nd_t*gae_{t+1}   (gae_T = 0)
//   adv = gae ; ret = gae + v.  Output: [adv | ret].
//
// R3: BB=4 (grid 2048 one-warp blocks -> ~13.8 warps/SM) to double memory
//     concurrency. Register-prefetch pipeline retained. Recurrence uses 16
//     of 32 lanes (tiny phase; concurrency in the memory phases dominates).

#define GAMMA_F  0.99f
#define LAMBDA_F 0.95f

constexpr int B = 8192;
constexpr int T = 256;
constexpr int A = 4;
constexpr int ROW4 = T * A / 4;      // 256 float4 per batch row

constexpr int BB = 4;                // batches per block
constexpr int TC = 16;               // t-steps per chunk
constexpr int THREADS = 32;          // one warp
constexpr int SROW = TC * A + 4;     // 68: bank = (4bb+4dt+a)%32, conflict-free
constexpr int K = (BB * TC) / THREADS;  // float4 loads per thread per array = 2

struct Chunk {
    float4 dl[K];
    float4 nd[K];
    float4 v [K];
};

__device__ __forceinline__ Chunk load_chunk(const float4* __restrict__ reward,
                                            const float4* __restrict__ term,
                                            const float4* __restrict__ value,
                                            const float4* __restrict__ nxtval,
                                            int b0, int t0, int lane)
{
    Chunk c;
    #pragma unroll
    for (int k = 0; k < K; k++) {
        const int f   = lane + k * THREADS;  // 0..63
        const int row = f >> 4;              // local batch 0..3
        const int col = f & 15;              // float4 (= t-step) within chunk
        const int g   = (b0 + row) * ROW4 + t0 + col;

        const float4 r  = reward[g];
        const float4 tm = term[g];
        const float4 v  = value[g];
        const float4 nv = nxtval[g];

        float4 nd, dl;
        nd.x = 1.0f - tm.x;  nd.y = 1.0f - tm.y;
        nd.z = 1.0f - tm.z;  nd.w = 1.0f - tm.w;
        dl.x = fmaf(GAMMA_F * nv.x, nd.x, r.x) - v.x;
        dl.y = fmaf(GAMMA_F * nv.y, nd.y, r.y) - v.y;
        dl.z = fmaf(GAMMA_F * nv.z, nd.z, r.z) - v.z;
        dl.w = fmaf(GAMMA_F * nv.w, nd.w, r.w) - v.w;

        c.dl[k] = dl;  c.nd[k] = nd;  c.v[k] = v;
    }
    return c;
}

__global__ __launch_bounds__(THREADS)
void gae_kernel(const float4* __restrict__ reward,
                const float4* __restrict__ term,
                const float4* __restrict__ value,
                const float4* __restrict__ nxtval,
                float4* __restrict__ adv_out,
                float4* __restrict__ ret_out)
{
    __shared__ float s_dl [BB * SROW];
    __shared__ float s_nd [BB * SROW];
    __shared__ float s_v  [BB * SROW];
    __shared__ float s_adv[BB * SROW];

    const int lane = threadIdx.x;
    const int b0   = blockIdx.x * BB;
    const int bb   = lane >> 2;          // 0..7; only bb<4 active in recurrence
    const int a    = lane & 3;

    float gae = 0.0f;

    // prologue: prefetch last chunk
    Chunk cur = load_chunk(reward, term, value, nxtval, b0, T - TC, lane);

    #pragma unroll 2
    for (int t0 = T - TC; t0 >= 0; t0 -= TC) {
        // ---- stage current chunk regs -> smem ----
        #pragma unroll
        for (int k = 0; k < K; k++) {
            const int f   = lane + k * THREADS;
            const int row = f >> 4;
            const int col = f & 15;
            const int s   = row * SROW + col * 4;
            *reinterpret_cast<float4*>(&s_dl[s]) = cur.dl[k];
            *reinterpret_cast<float4*>(&s_nd[s]) = cur.nd[k];
            *reinterpret_cast<float4*>(&s_v [s]) = cur.v [k];
        }

        // ---- issue next chunk's LDGs now; latency overlaps recurrence ----
        Chunk nxt;
        if (t0 > 0)
            nxt = load_chunk(reward, term, value, nxtval, b0, t0 - TC, lane);

        __syncwarp();

        // ---- serial backward recurrence (one sequence per active lane) ----
        if (lane < BB * A) {
            float g = gae;
            #pragma unroll
            for (int dt = TC - 1; dt >= 0; dt--) {
                const int s = bb * SROW + dt * 4 + a;
                g = fmaf((GAMMA_F * LAMBDA_F) * s_nd[s], g, s_dl[s]);
                s_adv[s] = g;
            }
            gae = g;
        }
        __syncwarp();

        // ---- drain: coalesced float4 stores (ret recomputed here) ----
        #pragma unroll
        for (int k = 0; k < K; k++) {
            const int f   = lane + k * THREADS;
            const int row = f >> 4;
            const int col = f & 15;
            const int g   = (b0 + row) * ROW4 + t0 + col;
            const int s   = row * SROW + col * 4;
            const float4 ad = *reinterpret_cast<const float4*>(&s_adv[s]);
            const float4 vv = *reinterpret_cast<const float4*>(&s_v [s]);
            float4 rt;
            rt.x = ad.x + vv.x;  rt.y = ad.y + vv.y;
            rt.z = ad.z + vv.z;  rt.w = ad.w + vv.w;
            adv_out[g] = ad;
            ret_out[g] = rt;
        }
        __syncwarp();  // protect smem before next stage overwrites

        if (t0 > 0) cur = nxt;
    }
}

extern "C" void kernel_launch(void* const* d_in, const int* in_sizes, int n_in,
                              void* d_out, int out_size)
{
    const float4* reward = (const float4*)d_in[0];
    const float4* term   = (const float4*)d_in[1];
    const float4* value  = (const float4*)d_in[2];
    const float4* nxtval = (const float4*)d_in[3];

    float* out = (float*)d_out;
    float4* adv = (float4*)out;
    float4* ret = (float4*)(out + (size_t)B * T * A);

    gae_kernel<<<B / BB, THREADS>>>(reward, term, value, nxtval, adv, ret);
}